// round 12
// baseline (speedup 1.0000x reference)
#include <cuda_runtime.h>
#include <cuda_fp16.h>
#include <cstdint>
#include <cstddef>

#define BATCH   8192
#define IN_DIM  4096
#define HID     16384
#define KSEL    64
#define HB      520          // per-row histogram stride (513 used)

// -------- scratch (allocation-free: __device__ globals) --------
__device__ __half    g_wdecT[(size_t)HID * IN_DIM];  // W_dec^T fp16 [HID, IN_DIM]
__device__ __half    g_xh[(size_t)BATCH * IN_DIM];   // fp16(x)
__device__ __half    g_wh[(size_t)HID * IN_DIM];     // fp16(W_enc)
__device__ uint32_t  g_hist[(size_t)BATCH * HB];     // per-row feature histograms

// ============================================================================
// zero per-row histograms
// ============================================================================
__global__ __launch_bounds__(1024) void zero_hist_kernel()
{
    size_t i = (size_t)blockIdx.x * 1024 + threadIdx.x;
    if (i < (size_t)BATCH * HB) g_hist[i] = 0u;
}

// ============================================================================
// fp32 -> fp16 conversion
// ============================================================================
__global__ __launch_bounds__(256) void to_half_kernel(
    const float* __restrict__ src, __half* __restrict__ dst, size_t n4)
{
    size_t i = (size_t)blockIdx.x * 256 + threadIdx.x;
    if (i >= n4) return;
    float4 v = ((const float4*)src)[i];
    __half2* d = (__half2*)dst;
    d[2 * i]     = __floats2half2_rn(v.x, v.y);
    d[2 * i + 1] = __floats2half2_rn(v.z, v.w);
}

// ============================================================================
// transpose W_dec [IN_DIM, HID] -> g_wdecT (fp16) [HID, IN_DIM]
// ============================================================================
__global__ void wdec_transpose(const float* __restrict__ W)
{
    __shared__ float tile[32][33];
    int h0 = blockIdx.x * 32;
    int d0 = blockIdx.y * 32;
    int tx = threadIdx.x, ty = threadIdx.y;
#pragma unroll
    for (int r = 0; r < 32; r += 8)
        tile[ty + r][tx] = W[(size_t)(d0 + ty + r) * HID + (h0 + tx)];
    __syncthreads();
#pragma unroll
    for (int r = 0; r < 32; r += 8)
        g_wdecT[(size_t)(h0 + ty + r) * IN_DIM + (d0 + tx)] =
            __float2half_rn(tile[tx][ty + r]);
}

// ============================================================================
// Encoder GEMM: fp16 HMMA, fp32 accum; epilogue also builds per-row histograms
//   BM=128, BN=128, BK=64, 8 warps, warp tile 64x32, 3-stage, 2 CTAs/SM.
// ============================================================================
#define GBM 128
#define GBN 128
#define GBK 64
#define NSTAGE 3
#define ROWB 144
#define A_ST_B (GBM * ROWB)
#define B_ST_B (GBN * ROWB)
#define STG_B  (A_ST_B + B_ST_B)
#define GEMM_SMEM (NSTAGE * STG_B)   // 110592
#define K_ITERS (IN_DIM / GBK)
#define GEMM_THREADS 256

__device__ __forceinline__ uint32_t smem_u32(const void* p) {
    uint32_t a;
    asm("{ .reg .u64 t; cvta.to.shared.u64 t, %1; cvt.u32.u64 %0, t; }" : "=r"(a) : "l"(p));
    return a;
}
#define CP_ASYNC16(dst, src) \
    asm volatile("cp.async.cg.shared.global [%0], [%1], 16;" :: "r"(dst), "l"(src))
#define CP_COMMIT() asm volatile("cp.async.commit_group;" ::: "memory")
#define CP_WAIT1()  asm volatile("cp.async.wait_group 1;" ::: "memory")

#define LDSM_X4(r0, r1, r2, r3, addr) \
    asm volatile("ldmatrix.sync.aligned.m8n8.x4.shared.b16 {%0,%1,%2,%3}, [%4];" \
                 : "=r"(r0), "=r"(r1), "=r"(r2), "=r"(r3) : "r"(addr))

#define MMA16816(d, a, b0, b1) \
    asm volatile("mma.sync.aligned.m16n8k16.row.col.f32.f16.f16.f32 " \
                 "{%0,%1,%2,%3}, {%4,%5,%6,%7}, {%8,%9}, {%0,%1,%2,%3};" \
                 : "+f"((d)[0]), "+f"((d)[1]), "+f"((d)[2]), "+f"((d)[3]) \
                 : "r"((a)[0]), "r"((a)[1]), "r"((a)[2]), "r"((a)[3]), \
                   "r"(b0), "r"(b1))

__device__ __forceinline__ void hist_acc(int row, float f)
{
    if (f >= 2.0f) {
        uint32_t bin = (__float_as_uint(f) >> 15) - 0x8000u;
        if (bin > 512u) bin = 512u;           // >= 8.0 bucket
        atomicAdd(&g_hist[(size_t)row * HB + bin], 1u);
    }
}

__device__ __forceinline__ void gemm_load_stage(uint32_t sbase, int stage, int k0,
                                                int m0, int n0, int tid)
{
    uint32_t sb = sbase + stage * STG_B;
#pragma unroll
    for (int t = 0; t < 4; t++) {
        int i = tid + t * GEMM_THREADS;
        int row = i >> 3, c = i & 7;
        const __half* src = g_xh + (size_t)(m0 + row) * IN_DIM + k0 + c * 8;
        CP_ASYNC16(sb + row * ROWB + c * 16, src);
    }
    uint32_t sbB = sb + A_ST_B;
#pragma unroll
    for (int t = 0; t < 4; t++) {
        int i = tid + t * GEMM_THREADS;
        int row = i >> 3, c = i & 7;
        const __half* src = g_wh + (size_t)(n0 + row) * IN_DIM + k0 + c * 8;
        CP_ASYNC16(sbB + row * ROWB + c * 16, src);
    }
}

__global__ __launch_bounds__(GEMM_THREADS, 2) void encoder_gemm_hmma(
    const float* __restrict__ bias, float* __restrict__ out_sf)
{
    extern __shared__ __align__(128) char smem[];
    uint32_t sbase = smem_u32(smem);
    const int tid  = threadIdx.x;
    const int lane = tid & 31;
    const int wid  = tid >> 5;
    const int warp_m = wid & 1;
    const int warp_n = wid >> 1;

    int pid = blockIdx.x;
    int nb = (pid >> 3) & 127;
    int mb = (pid & 7) | ((pid >> 10) << 3);
    int m0 = mb * GBM, n0 = nb * GBN;

    const int g = lane >> 3;
    const int rA = warp_m * 64 + ((g & 1) << 3) + (lane & 7);
    const int cA = (g >> 1) << 4;
    const int rB = warp_n * 32 + ((g >> 1) << 3) + (lane & 7);
    const int cB = (g & 1) << 4;

    float acc[4][4][4];
#pragma unroll
    for (int i = 0; i < 4; i++)
#pragma unroll
        for (int j = 0; j < 4; j++)
#pragma unroll
            for (int q = 0; q < 4; q++) acc[i][j][q] = 0.0f;

    gemm_load_stage(sbase, 0, 0, m0, n0, tid); CP_COMMIT();
    gemm_load_stage(sbase, 1, GBK, m0, n0, tid); CP_COMMIT();

    for (int it = 0; it < K_ITERS; it++) {
        int cur = it % 3;
        CP_WAIT1();
        __syncthreads();

        if (it + 2 < K_ITERS)
            gemm_load_stage(sbase, (it + 2) % 3, (it + 2) * GBK, m0, n0, tid);
        CP_COMMIT();

        uint32_t aST = sbase + cur * STG_B;
        uint32_t bST = aST + A_ST_B;

#pragma unroll
        for (int ks = 0; ks < 4; ks++) {
            uint32_t koff = (uint32_t)(ks * 32);
            uint32_t af[4][4], bf[2][4];
#pragma unroll
            for (int mf = 0; mf < 4; mf++) {
                uint32_t ad = aST + (uint32_t)((rA + mf * 16) * ROWB + cA) + koff;
                LDSM_X4(af[mf][0], af[mf][1], af[mf][2], af[mf][3], ad);
            }
#pragma unroll
            for (int nf = 0; nf < 2; nf++) {
                uint32_t bd = bST + (uint32_t)((rB + nf * 16) * ROWB + cB) + koff;
                LDSM_X4(bf[nf][0], bf[nf][1], bf[nf][2], bf[nf][3], bd);
            }
#pragma unroll
            for (int mf = 0; mf < 4; mf++)
#pragma unroll
                for (int nf = 0; nf < 2; nf++) {
                    MMA16816(acc[mf][nf * 2],     af[mf], bf[nf][0], bf[nf][1]);
                    MMA16816(acc[mf][nf * 2 + 1], af[mf], bf[nf][2], bf[nf][3]);
                }
        }
    }

    // epilogue: bias + relu -> out_sf, plus per-row histogram accumulation
    int rbase = m0 + warp_m * 64 + (lane >> 2);
    int cbase = n0 + warp_n * 32 + ((lane & 3) << 1);
#pragma unroll
    for (int mf = 0; mf < 4; mf++) {
#pragma unroll
        for (int nf = 0; nf < 4; nf++) {
            int col = cbase + nf * 8;
            float b0 = __ldg(&bias[col]);
            float b1 = __ldg(&bias[col + 1]);
            int r0 = rbase + mf * 16;
            float2 v0, v1;
            v0.x = fmaxf(acc[mf][nf][0] + b0, 0.0f);
            v0.y = fmaxf(acc[mf][nf][1] + b1, 0.0f);
            v1.x = fmaxf(acc[mf][nf][2] + b0, 0.0f);
            v1.y = fmaxf(acc[mf][nf][3] + b1, 0.0f);
            *(float2*)(out_sf + (size_t)r0 * HID + col)       = v0;
            *(float2*)(out_sf + (size_t)(r0 + 8) * HID + col) = v1;
            hist_acc(r0, v0.x);     hist_acc(r0, v0.y);
            hist_acc(r0 + 8, v1.x); hist_acc(r0 + 8, v1.y);
        }
    }
}

// ============================================================================
// top-k v5 + fused decode:
//   histogram comes precomputed from GEMM epilogue -> only ONE full-row sweep.
//   After selection+compaction (to smem), the same CTA decodes the recon row.
// ============================================================================
#define TOPK_THREADS 512
#define NBINS 1024
#define ERRB 3e-3f
#define ZCAP 128
#define NWORDS (HID / 32)    // 512

__device__ __forceinline__ float refine_dot_warp(const float* __restrict__ xr,
                                                 const float* __restrict__ wr,
                                                 float b, int lane)
{
    float s = 0.f, c = 0.f;
    for (int t = 0; t < 16; t++) {
        int base = t * 256 + lane;
        float r = xr[base] * wr[base];
#pragma unroll
        for (int j = 1; j < 8; j++)
            r = fmaf(xr[base + 32 * j], wr[base + 32 * j], r);
        float tt = s + r;
        float z = tt - s;
        float e = (s - (tt - z)) + (r - z);
        c += e; s = tt;
    }
#pragma unroll
    for (int off = 16; off; off >>= 1) {
        float s2 = __shfl_down_sync(0xffffffffu, s, off);
        float c2 = __shfl_down_sync(0xffffffffu, c, off);
        float tt = s + s2;
        float z = tt - s;
        float e = (s - (tt - z)) + (s2 - z);
        c += c2 + e; s = tt;
    }
    float d = s + c;
    return fmaxf(d + b, 0.0f);
}

__device__ __forceinline__ int scan_bins_top(const uint32_t* hist, int top,
                                             int base, int lane)
{
    int dbin = -1;
    int nrounds = (top + 31) / 32;
    for (int r = 0; r < nrounds; r++) {
        int bin = top - 1 - (r * 32 + lane);
        int h = (bin >= 0) ? (int)hist[bin] : 0;
        int pre = h;
#pragma unroll
        for (int off = 1; off < 32; off <<= 1) {
            int t = __shfl_up_sync(0xffffffffu, pre, off);
            if (lane >= off) pre += t;
        }
        int cum = base + pre;
        unsigned bal = __ballot_sync(0xffffffffu, (cum >= KSEL) && (bin >= 0));
        if (bal) {
            int l0 = __ffs(bal) - 1;
            dbin = top - 1 - (r * 32 + l0);
            break;
        }
        base += __shfl_sync(0xffffffffu, pre, 31);
    }
    return dbin;
}

__global__ __launch_bounds__(TOPK_THREADS) void topk_decode_kernel(
    float* __restrict__ out_sf,
    float* __restrict__ out_rec,
    const float* __restrict__ x,
    const float* __restrict__ W,
    const float* __restrict__ bias)
{
    __shared__ uint32_t hist[NBINS];
    __shared__ uint32_t keep[NWORDS];
    __shared__ int s_nhi, s_nzone, s_dbin, s_mode, s_big;
    __shared__ int   s_zidx[ZCAP];
    __shared__ float s_zval[ZCAP];
    __shared__ unsigned char s_keepz[ZCAP];
    __shared__ int s_wsum[16];
    __shared__ float s_cv[KSEL];
    __shared__ int   s_ci[KSEL];

    int row = blockIdx.x;
    int tid = threadIdx.x;
    int wid = tid >> 5, lane = tid & 31;
    float* orow = out_sf + (size_t)row * HID;

    // load precomputed histogram (513 words)
    for (int i = tid; i < 513; i += TOPK_THREADS)
        hist[i] = g_hist[(size_t)row * HB + i];
    if (tid == 0) { s_nhi = 0; s_nzone = 0; s_dbin = -1; s_mode = 0; }
    if (tid < KSEL) { s_cv[tid] = 0.0f; s_ci[tid] = 0; }
    __syncthreads();
    if (tid == 0) s_big = (int)hist[512];
    __syncthreads();

    if (wid == 0) {
        int d = scan_bins_top(hist, 512, s_big, lane);
        if (lane == 0) { s_dbin = d; if (d >= 0) s_mode = 1; }
    }
    __syncthreads();

    if (s_mode == 0) {
        // mode B (rare): row-sweep histogram [0.25, 8) on bits[30:16]
        hist[tid] = 0; hist[tid + TOPK_THREADS] = 0;
        __syncthreads();
        for (int i = tid; i < HID; i += TOPK_THREADS) {
            float f = orow[i];
            if (f >= 0.25f && f < 8.0f)
                atomicAdd(&hist[(__float_as_uint(f) >> 16) - 0x3E80u], 1u);
        }
        __syncthreads();
        if (wid == 0) {
            int d = scan_bins_top(hist, 640, s_big, lane);
            if (lane == 0) { s_dbin = d; if (d >= 0) s_mode = 2; else s_mode = 3; }
        }
        __syncthreads();
    }

    float B_lo, B_hi;
    if (s_mode == 1) {
        B_lo = __uint_as_float((uint32_t)(0x8000u + s_dbin) << 15);
        B_hi = __uint_as_float((uint32_t)(0x8000u + s_dbin + 1) << 15);
    } else if (s_mode == 2) {
        B_lo = __uint_as_float((uint32_t)(0x3E80u + s_dbin) << 16);
        B_hi = __uint_as_float((uint32_t)(0x3E80u + s_dbin + 1) << 16);
    } else {
        B_lo = 0.0f; B_hi = 0.25f;
    }
    float Thi = B_hi + 2.0f * ERRB;
    float Tlo = B_lo - 2.0f * ERRB;

    // single full-row sweep: classify + zero below-zone positives + keep bits
    {
        int myhi = 0;
        for (int w = wid; w < NWORDS; w += (TOPK_THREADS / 32)) {
            int i = w * 32 + lane;
            float f = orow[i];
            bool hi = (f > Thi);
            bool inz = false;
            if (!hi && f > 0.0f && f >= Tlo) {
                int p = atomicAdd(&s_nzone, 1);
                if (p < ZCAP) { s_zidx[p] = i; s_zval[p] = f; inz = true; }
            }
            myhi += hi;
            unsigned m = __ballot_sync(0xffffffffu, hi);
            if (lane == 0) keep[w] = m;
            if (!hi && !inz && __float_as_uint(f) != 0u) orow[i] = 0.0f;
        }
#pragma unroll
        for (int off = 16; off; off >>= 1) myhi += __shfl_down_sync(0xffffffffu, myhi, off);
        if (lane == 0 && myhi) atomicAdd(&s_nhi, myhi);
    }
    __syncthreads();

    int nhi  = s_nhi;
    int nzr  = s_nzone;
    bool ovf = (nzr > ZCAP);
    int nz   = ovf ? ZCAP : nzr;
    int need = KSEL - nhi;

    bool did_refine = (!ovf && nz != need && nz > 0 && need > 0);
    if (did_refine) {
        const float* xr = x + (size_t)row * IN_DIM;
        for (int j = wid; j < nz; j += (TOPK_THREADS / 32)) {
            int h = s_zidx[j];
            float v = refine_dot_warp(xr, W + (size_t)h * IN_DIM, __ldg(&bias[h]), lane);
            if (lane == 0) s_zval[j] = v;
        }
    }
    __syncthreads();

    // rank selection among zone (exact top-`need`, index tiebreak)
    if (tid < nz) {
        bool km;
        if (!ovf && nz == need) km = true;
        else if (need <= 0) km = false;
        else {
            float mv = s_zval[tid]; int mi = s_zidx[tid];
            int better = 0;
            for (int j = 0; j < nz; j++) {
                if (j == tid) continue;
                if (s_zval[j] > mv || (s_zval[j] == mv && s_zidx[j] < mi)) better++;
            }
            km = (better < need);
        }
        s_keepz[tid] = km ? 1 : 0;
    }
    __syncthreads();

    // patch zone elements
    if (tid < nz) {
        int i = s_zidx[tid];
        if (s_keepz[tid]) {
            orow[i] = s_zval[tid];
            atomicOr(&keep[i >> 5], 1u << (i & 31));
        } else {
            orow[i] = 0.0f;
        }
    }
    __syncthreads();

    // parallel compaction -> smem (s_cv, s_ci)
    {
        uint32_t m = keep[tid];
        int c = __popc(m);
        int pre = c;
#pragma unroll
        for (int off = 1; off < 32; off <<= 1) {
            int t = __shfl_up_sync(0xffffffffu, pre, off);
            if (lane >= off) pre += t;
        }
        if (lane == 31) s_wsum[wid] = pre;
        __syncthreads();
        if (wid == 0 && lane < 16) {
            int v = s_wsum[lane];
            int p = v;
#pragma unroll
            for (int off = 1; off < 16; off <<= 1) {
                int t = __shfl_up_sync(0xffffu, p, off);
                if (lane >= off) p += t;
            }
            s_wsum[lane] = p - v;
        }
        __syncthreads();
        int excl = s_wsum[wid] + pre - c;
        while (m) {
            int b = __ffs(m) - 1;
            m &= m - 1;
            if (excl < KSEL) {
                s_cv[excl] = orow[tid * 32 + b];
                s_ci[excl] = tid * 32 + b;
            }
            excl++;
        }
    }
    __syncthreads();

    // fused sparse decode: recon[row,:] = sum_j v_j * W_dec^T[h_j,:]
    {
        float acc[8];
#pragma unroll
        for (int q = 0; q < 8; q++) acc[q] = 0.0f;
        for (int j = 0; j < KSEL; j++) {
            float v = s_cv[j];
            uint4 t = ((const uint4*)(g_wdecT + (size_t)s_ci[j] * IN_DIM))[tid];
            float2 f0 = __half22float2(*(__half2*)&t.x);
            float2 f1 = __half22float2(*(__half2*)&t.y);
            float2 f2 = __half22float2(*(__half2*)&t.z);
            float2 f3 = __half22float2(*(__half2*)&t.w);
            acc[0] = fmaf(v, f0.x, acc[0]);
            acc[1] = fmaf(v, f0.y, acc[1]);
            acc[2] = fmaf(v, f1.x, acc[2]);
            acc[3] = fmaf(v, f1.y, acc[3]);
            acc[4] = fmaf(v, f2.x, acc[4]);
            acc[5] = fmaf(v, f2.y, acc[5]);
            acc[6] = fmaf(v, f3.x, acc[6]);
            acc[7] = fmaf(v, f3.y, acc[7]);
        }
        float* op = out_rec + (size_t)row * IN_DIM + tid * 8;
        *(float4*)op       = *(float4*)(&acc[0]);
        *(float4*)(op + 4) = *(float4*)(&acc[4]);
    }
}

// ============================================================================
// launch
// ============================================================================
extern "C" void kernel_launch(void* const* d_in, const int* in_sizes, int n_in,
                              void* d_out, int out_size)
{
    const float* x     = (const float*)d_in[0];
    const float* W_enc = (const float*)d_in[1];
    const float* b_enc = (const float*)d_in[2];
    const float* W_dec = (const float*)d_in[3];

    float* out_sf  = (float*)d_out;
    float* out_rec = out_sf + (size_t)BATCH * HID;

    __half *xh, *wh;
    cudaGetSymbolAddress((void**)&xh, g_xh);
    cudaGetSymbolAddress((void**)&wh, g_wh);

    // 0) zero per-row histograms
    zero_hist_kernel<<<((unsigned)((size_t)BATCH * HB + 1023) / 1024), 1024>>>();

    // 1) fp16 conversions
    size_t nx4 = (size_t)BATCH * IN_DIM / 4;
    size_t nw4 = (size_t)HID * IN_DIM / 4;
    to_half_kernel<<<(unsigned)(nx4 / 256), 256>>>(x, xh, nx4);
    to_half_kernel<<<(unsigned)(nw4 / 256), 256>>>(W_enc, wh, nw4);

    // 2) transpose W_dec -> fp16
    wdec_transpose<<<dim3(HID / 32, IN_DIM / 32), dim3(32, 8)>>>(W_dec);

    // 3) encoder GEMM (HMMA, 2 CTAs/SM) + in-epilogue histograms -> out_sf
    cudaFuncSetAttribute(encoder_gemm_hmma, cudaFuncAttributeMaxDynamicSharedMemorySize,
                         GEMM_SMEM);
    encoder_gemm_hmma<<<(HID / GBN) * (BATCH / GBM), GEMM_THREADS, GEMM_SMEM>>>(b_enc, out_sf);

    // 4) top-k (bracket from precomputed hist + exact refinement) + fused decode
    topk_decode_kernel<<<BATCH, TOPK_THREADS>>>(out_sf, out_rec, x, W_enc, b_enc);
}